// round 14
// baseline (speedup 1.0000x reference)
#include <cuda_runtime.h>

// Problem constants
#define B_  2
#define N_  2048
#define D_  1024
#define H_  16
#define DH  64
#define M_  (B_ * N_)   // 4096 rows

// Scratch (device globals — no allocation allowed)
__device__ float g_Q[M_ * D_];
__device__ float g_K[M_ * D_];
__device__ float g_V[M_ * D_];
__device__ float g_C[M_ * D_];

// ---------------------------------------------------------------------------
// Packed f32x2 helpers (Blackwell FFMA2 — 2 FMAs per fma-pipe instruction)
// ---------------------------------------------------------------------------
typedef unsigned long long u64;

__device__ __forceinline__ u64 pack2(float x, float y) {
    u64 r; asm("mov.b64 %0, {%1,%2};" : "=l"(r) : "f"(x), "f"(y)); return r;
}
__device__ __forceinline__ float2 unpack2(u64 v) {
    float2 r; asm("mov.b64 {%0,%1}, %2;" : "=f"(r.x), "=f"(r.y) : "l"(v)); return r;
}
__device__ __forceinline__ u64 ffma2(u64 a, u64 b, u64 c) {
    u64 d; asm("fma.rn.f32x2 %0, %1, %2, %3;" : "=l"(d) : "l"(a), "l"(b), "l"(c)); return d;
}
__device__ __forceinline__ u64 fmul2(u64 a, u64 b) {
    u64 d; asm("mul.rn.f32x2 %0, %1, %2;" : "=l"(d) : "l"(a), "l"(b)); return d;
}
__device__ __forceinline__ u64 swap2(u64 v) {   // {lo,hi} -> {hi,lo}
    u64 r;
    asm("{\n\t.reg .b32 lo, hi;\n\t"
        "mov.b64 {lo, hi}, %1;\n\t"
        "mov.b64 %0, {hi, lo};\n\t}"
        : "=l"(r) : "l"(v));
    return r;
}

// ---------------------------------------------------------------------------
// NT SGEMM tile, FFMA2 diagonal/anti-diagonal microkernel:
//   C[m][n] = sum_k A[m][k] * W[n][k] (+ bias[n])
// BM=BN=128, BK=8, 256 threads, 8x8 per thread as 4x4 PAIR blocks.
// For a-pair {a0,a1} and w-pair {w0,w1}:
//   accD += {a0,a1}*{w0,w1}  -> diag   (a0w0, a1w1)
//   accA += {a0,a1}*{w1,w0}  -> anti   (a0w1, a1w0)
// Operands come straight from 4 LDS.128 per k-step (no duplicated smem).
// ---------------------------------------------------------------------------
__device__ __forceinline__ void gemm_tile(const float* __restrict__ A,
                                          const float* __restrict__ W,
                                          float* __restrict__ C,
                                          const float* __restrict__ bias)
{
    __shared__ float As[8][128];
    __shared__ float Ws[8][128];

    const int tid = threadIdx.x;          // 0..255
    const int tx  = tid & 15;             // 0..15 (N direction)
    const int ty  = tid >> 4;             // 0..15 (M direction)
    const int mbase = blockIdx.y * 128;
    const int nbase = blockIdx.x * 128;

    // Global-load mapping: each thread loads one float4 per tile per matrix.
    const int lr = tid >> 1;              // row within 128-row tile
    const int lc = (tid & 1) * 4;         // 0 or 4 within the 8-wide K slab
    const float* Ap = A + (size_t)(mbase + lr) * D_ + lc;
    const float* Wp = W + (size_t)(nbase + lr) * D_ + lc;

    u64 accD[4][4], accA[4][4];
    #pragma unroll
    for (int i = 0; i < 4; i++)
        #pragma unroll
        for (int j = 0; j < 4; j++) { accD[i][j] = 0ull; accA[i][j] = 0ull; }

    float4 av = *(const float4*)(Ap);
    float4 wv = *(const float4*)(Wp);

    for (int kb = 0; kb < D_; kb += 8) {
        // store current slab (transposed: [k][row])
        As[lc + 0][lr] = av.x; As[lc + 1][lr] = av.y;
        As[lc + 2][lr] = av.z; As[lc + 3][lr] = av.w;
        Ws[lc + 0][lr] = wv.x; Ws[lc + 1][lr] = wv.y;
        Ws[lc + 2][lr] = wv.z; Ws[lc + 3][lr] = wv.w;
        __syncthreads();

        // prefetch next slab while computing
        if (kb + 8 < D_) {
            av = *(const float4*)(Ap + kb + 8);
            wv = *(const float4*)(Wp + kb + 8);
        }

        #pragma unroll
        for (int k = 0; k < 8; k++) {
            ulonglong2 aA = *(const ulonglong2*)&As[k][ty * 8];      // {a0,a1},{a2,a3}
            ulonglong2 aB = *(const ulonglong2*)&As[k][ty * 8 + 4];  // {a4,a5},{a6,a7}
            ulonglong2 wA = *(const ulonglong2*)&Ws[k][tx * 8];
            ulonglong2 wB = *(const ulonglong2*)&Ws[k][tx * 8 + 4];
            u64 a2[4] = { aA.x, aA.y, aB.x, aB.y };
            u64 w2[4] = { wA.x, wA.y, wB.x, wB.y };
            u64 ws[4];
            #pragma unroll
            for (int j = 0; j < 4; j++) ws[j] = swap2(w2[j]);

            #pragma unroll
            for (int i = 0; i < 4; i++)
                #pragma unroll
                for (int j = 0; j < 4; j++) {
                    accD[i][j] = ffma2(a2[i], w2[j], accD[i][j]);
                    accA[i][j] = ffma2(a2[i], ws[j], accA[i][j]);
                }
        }
        __syncthreads();
    }

    // Epilogue: unscramble diag/anti pairs into rows, add bias, store float4.
    #pragma unroll
    for (int ip = 0; ip < 4; ip++) {
        const size_t r0 = (size_t)(mbase + ty * 8 + 2 * ip) * D_;
        const size_t r1 = r0 + D_;
        #pragma unroll
        for (int jh = 0; jh < 2; jh++) {               // two float4 per row
            const int c = nbase + tx * 8 + jh * 4;
            float2 d0 = unpack2(accD[ip][2 * jh]);     // cols c, c+1 (diag)
            float2 x0 = unpack2(accA[ip][2 * jh]);     // cols c+1, c (anti)
            float2 d1 = unpack2(accD[ip][2 * jh + 1]); // cols c+2, c+3
            float2 x1 = unpack2(accA[ip][2 * jh + 1]);
            float4 row0 = make_float4(d0.x, x0.x, d1.x, x1.x);
            float4 row1 = make_float4(x0.y, d0.y, x1.y, d1.y);
            if (bias) {
                float4 bb = *(const float4*)(bias + c);
                row0.x += bb.x; row0.y += bb.y; row0.z += bb.z; row0.w += bb.w;
                row1.x += bb.x; row1.y += bb.y; row1.z += bb.z; row1.w += bb.w;
            }
            *(float4*)(C + r0 + c) = row0;
            *(float4*)(C + r1 + c) = row1;
        }
    }
}

// Fused QKV projection: blockIdx.z selects which weight/output (x tiles L2-shared).
__global__ void __launch_bounds__(256, 2) qkv_kernel(const float* __restrict__ x,
                                                     const float* __restrict__ Wq,
                                                     const float* __restrict__ Wk,
                                                     const float* __restrict__ Wv)
{
    const float* W;
    float* O;
    if (blockIdx.z == 0)      { W = Wq; O = g_Q; }
    else if (blockIdx.z == 1) { W = Wk; O = g_K; }
    else                      { W = Wv; O = g_V; }
    gemm_tile(x, W, O, nullptr);
}

// Output projection: out = ctx @ Wo^T + bo
__global__ void __launch_bounds__(256, 2) outproj_kernel(const float* __restrict__ Wo,
                                                         const float* __restrict__ bo,
                                                         float* __restrict__ out)
{
    gemm_tile(g_C, Wo, out, bo);
}

// ---------------------------------------------------------------------------
// Flash attention (fp32, FFMA2), double-buffered 16-row KV tiles.
// Grid: (N_/128, B_*H_). Block: 128 threads; each thread owns ONE query row:
//   q[64] and o[64] live in registers as 32 packed f32x2 each.
// ---------------------------------------------------------------------------
__global__ void __launch_bounds__(128) flash_kernel()
{
    __shared__ float Ks[2][16][64];
    __shared__ float Vs[2][16][64];

    const int bh = blockIdx.y;
    const int b  = bh >> 4;
    const int h  = bh & 15;
    const int n  = blockIdx.x * 128 + threadIdx.x;     // query row (always < 2048)
    const size_t row = (size_t)(b * N_ + n) * D_ + h * DH;

    // Load + pre-scale q into packed registers
    u64 q2[32];
    {
        const float sc = 0.125f;  // dh^-0.5 = 64^-0.5
        #pragma unroll
        for (int d4 = 0; d4 < 16; d4++) {
            float4 t = *(const float4*)(g_Q + row + d4 * 4);
            q2[2 * d4]     = pack2(t.x * sc, t.y * sc);
            q2[2 * d4 + 1] = pack2(t.z * sc, t.w * sc);
        }
    }

    u64 o2[32];
    #pragma unroll
    for (int i = 0; i < 32; i++) o2[i] = 0ull;   // bit pattern of (0.f, 0.f)
    float m = -1e30f;
    float l = 0.0f;

    const size_t kvbase = (size_t)b * N_ * D_ + h * DH;

    // Per-thread staging map: 2 float4 of K + 2 float4 of V per 16x64 tile.
    const int f0  = threadIdx.x;
    const int f1  = threadIdx.x + 128;
    const int jr0 = f0 >> 4, c40 = (f0 & 15) * 4;
    const int jr1 = f1 >> 4, c41 = (f1 & 15) * 4;
    const size_t off0 = (size_t)jr0 * D_ + c40;
    const size_t off1 = (size_t)jr1 * D_ + c41;

    float4 kr0, kr1, vr0, vr1;

    // Prologue: tile 0 into buffer 0.
    kr0 = *(const float4*)(g_K + kvbase + off0);
    kr1 = *(const float4*)(g_K + kvbase + off1);
    vr0 = *(const float4*)(g_V + kvbase + off0);
    vr1 = *(const float4*)(g_V + kvbase + off1);
    *(float4*)&Ks[0][jr0][c40] = kr0;
    *(float4*)&Ks[0][jr1][c41] = kr1;
    *(float4*)&Vs[0][jr0][c40] = vr0;
    *(float4*)&Vs[0][jr1][c41] = vr1;
    __syncthreads();

    const int T = N_ / 16;   // 128 tiles
    for (int t = 0; t < T; t++) {
        const int cur = t & 1;

        // Issue next tile's global loads; latency overlaps the compute below.
        if (t + 1 < T) {
            const size_t g = kvbase + (size_t)(t + 1) * 16 * D_;
            kr0 = *(const float4*)(g_K + g + off0);
            kr1 = *(const float4*)(g_K + g + off1);
            vr0 = *(const float4*)(g_V + g + off0);
            vr1 = *(const float4*)(g_V + g + off1);
        }

        // S = q . K_j (packed FFMA2, 4 independent accumulator chains)
        float s[16];
        float tmax = -1e30f;
        #pragma unroll
        for (int j = 0; j < 16; j++) {
            const ulonglong2* kp = (const ulonglong2*)&Ks[cur][j][0];  // LDS.128
            u64 a0 = 0ull, a1 = 0ull, a2 = 0ull, a3 = 0ull;
            #pragma unroll
            for (int e = 0; e < 16; e += 2) {
                ulonglong2 ka = kp[e];
                ulonglong2 kb = kp[e + 1];
                a0 = ffma2(q2[2 * e + 0], ka.x, a0);
                a1 = ffma2(q2[2 * e + 1], ka.y, a1);
                a2 = ffma2(q2[2 * e + 2], kb.x, a2);
                a3 = ffma2(q2[2 * e + 3], kb.y, a3);
            }
            float2 t0 = unpack2(a0), t1 = unpack2(a1);
            float2 t2 = unpack2(a2), t3 = unpack2(a3);
            s[j] = ((t0.x + t0.y) + (t1.x + t1.y)) + ((t2.x + t2.y) + (t3.x + t3.y));
            tmax = fmaxf(tmax, s[j]);
        }

        // Online softmax update
        const float mnew = fmaxf(m, tmax);
        const float corr = __expf(m - mnew);   // first iter: exp(-huge) = 0
        m = mnew;
        float ps = 0.0f;
        #pragma unroll
        for (int j = 0; j < 16; j++) { s[j] = __expf(s[j] - mnew); ps += s[j]; }
        l = l * corr + ps;

        const u64 c2 = pack2(corr, corr);
        #pragma unroll
        for (int i = 0; i < 32; i++) o2[i] = fmul2(o2[i], c2);

        // O += P . V (packed FFMA2)
        #pragma unroll
        for (int j = 0; j < 16; j++) {
            const u64 p2 = pack2(s[j], s[j]);
            const ulonglong2* vp = (const ulonglong2*)&Vs[cur][j][0];
            #pragma unroll
            for (int e = 0; e < 16; e++) {
                ulonglong2 vv = vp[e];
                o2[2 * e]     = ffma2(p2, vv.x, o2[2 * e]);
                o2[2 * e + 1] = ffma2(p2, vv.y, o2[2 * e + 1]);
            }
        }

        // Store prefetched tile into the other buffer; barrier covers both
        // "tile t fully consumed" and "tile t+1 visible".
        if (t + 1 < T) {
            const int nxt = 1 - cur;
            *(float4*)&Ks[nxt][jr0][c40] = kr0;
            *(float4*)&Ks[nxt][jr1][c41] = kr1;
            *(float4*)&Vs[nxt][jr0][c40] = vr0;
            *(float4*)&Vs[nxt][jr1][c41] = vr1;
        }
        __syncthreads();
    }

    // Normalize and write context (same [row, h*64 + d] layout as Q)
    const float inv = 1.0f / l;
    const u64 i2 = pack2(inv, inv);
    #pragma unroll
    for (int e = 0; e < 16; e++) {
        ulonglong2 w;
        w.x = fmul2(o2[2 * e],     i2);
        w.y = fmul2(o2[2 * e + 1], i2);
        *(ulonglong2*)(g_C + row + e * 4) = w;
    }
}

// ---------------------------------------------------------------------------
// Launch
// ---------------------------------------------------------------------------
extern "C" void kernel_launch(void* const* d_in, const int* in_sizes, int n_in,
                              void* d_out, int out_size)
{
    (void)in_sizes; (void)n_in; (void)out_size;
    const float* x  = (const float*)d_in[0];
    const float* Wq = (const float*)d_in[1];
    const float* Wk = (const float*)d_in[2];
    const float* Wv = (const float*)d_in[3];
    const float* Wo = (const float*)d_in[4];
    const float* bo = (const float*)d_in[5];
    float* out = (float*)d_out;

    dim3 gq(D_ / 128, M_ / 128, 3);      // 8 x 32 x 3
    qkv_kernel<<<gq, 256>>>(x, Wq, Wk, Wv);

    dim3 ga(N_ / 128, B_ * H_);          // 16 x 32
    flash_kernel<<<ga, 128>>>();

    dim3 go(D_ / 128, M_ / 128);         // 8 x 32
    outproj_kernel<<<go, 256>>>(Wo, bo, out);
}

// round 16
// speedup vs baseline: 1.3365x; 1.3365x over previous
#include <cuda_runtime.h>
#include <cuda_bf16.h>

// Problem constants
#define B_  2
#define N_  2048
#define D_  1024
#define H_  16
#define DH  64
#define M_  (B_ * N_)   // 4096 rows

#define SZ_X (M_ * D_)  // 4194304
#define SZ_W (D_ * D_)  // 1048576

// Scratch (device globals — no allocation allowed)
__device__ float g_Q[SZ_X];
__device__ float g_K[SZ_X];
__device__ float g_V[SZ_X];
// bf16 split operands (hi/lo) for tensor-core GEMMs
__device__ __nv_bfloat16 s_xh[SZ_X], s_xl[SZ_X];
__device__ __nv_bfloat16 s_wh[4][SZ_W], s_wl[4][SZ_W];   // Wq,Wk,Wv,Wo
__device__ __nv_bfloat16 s_ch[SZ_X], s_cl[SZ_X];          // attention output split

typedef unsigned long long u64;
typedef unsigned int u32;

// ---------------------------------------------------------------------------
// Packed f32x2 helpers (flash kernel)
// ---------------------------------------------------------------------------
__device__ __forceinline__ u64 pack2(float x, float y) {
    u64 r; asm("mov.b64 %0, {%1,%2};" : "=l"(r) : "f"(x), "f"(y)); return r;
}
__device__ __forceinline__ float2 unpack2(u64 v) {
    float2 r; asm("mov.b64 {%0,%1}, %2;" : "=f"(r.x), "=f"(r.y) : "l"(v)); return r;
}
__device__ __forceinline__ u64 ffma2(u64 a, u64 b, u64 c) {
    u64 d; asm("fma.rn.f32x2 %0, %1, %2, %3;" : "=l"(d) : "l"(a), "l"(b), "l"(c)); return d;
}
__device__ __forceinline__ u64 fmul2(u64 a, u64 b) {
    u64 d; asm("mul.rn.f32x2 %0, %1, %2;" : "=l"(d) : "l"(a), "l"(b)); return d;
}

// ---------------------------------------------------------------------------
// HMMA plumbing (all plain sm_80+ PTX — compiles for bare sm_103)
// ---------------------------------------------------------------------------
__device__ __forceinline__ u32 smem_u32(const void* p) {
    u32 a;
    asm("{ .reg .u64 t; cvta.to.shared.u64 t, %1; cvt.u32.u64 %0, t; }"
        : "=r"(a) : "l"(p));
    return a;
}
__device__ __forceinline__ void ldm_x4(u32 addr, u32& r0, u32& r1, u32& r2, u32& r3) {
    asm volatile("ldmatrix.sync.aligned.m8n8.x4.shared.b16 {%0,%1,%2,%3}, [%4];"
                 : "=r"(r0), "=r"(r1), "=r"(r2), "=r"(r3) : "r"(addr));
}
__device__ __forceinline__ void ldm_x2(u32 addr, u32& r0, u32& r1) {
    asm volatile("ldmatrix.sync.aligned.m8n8.x2.shared.b16 {%0,%1}, [%2];"
                 : "=r"(r0), "=r"(r1) : "r"(addr));
}
__device__ __forceinline__ void mma16816(float* d, const u32* a, const u32* b) {
    asm volatile("mma.sync.aligned.m16n8k16.row.col.f32.bf16.bf16.f32 "
                 "{%0,%1,%2,%3}, {%4,%5,%6,%7}, {%8,%9}, {%0,%1,%2,%3};"
                 : "+f"(d[0]), "+f"(d[1]), "+f"(d[2]), "+f"(d[3])
                 : "r"(a[0]), "r"(a[1]), "r"(a[2]), "r"(a[3]),
                   "r"(b[0]), "r"(b[1]));
}
__device__ __forceinline__ void cp16(u32 dst, const void* src) {
    asm volatile("cp.async.cg.shared.global [%0], [%1], 16;" :: "r"(dst), "l"(src));
}
#define CP_COMMIT() asm volatile("cp.async.commit_group;")
#define CP_WAIT1()  asm volatile("cp.async.wait_group 1;")
#define CP_WAIT0()  asm volatile("cp.async.wait_group 0;")

// ---------------------------------------------------------------------------
// HMMA GEMM: C[m][n] = sum_k A[m][k]*W[n][k] (+bias), bf16x3 split,
// fp32 accumulate. BM=BN=128, BK=32, 256 threads (8 warps, 2x4 warp grid,
// warp tile 64x32). cp.async double-buffered smem, 80B-padded rows.
// ---------------------------------------------------------------------------
#define LDKB 80               // padded smem row pitch in bytes (40 bf16)
#define MATB (128 * LDKB)     // 10240 B per matrix per buffer
#define OAH 0
#define OAL (2 * MATB)
#define OWH (4 * MATB)
#define OWL (6 * MATB)
#define GSMEM (8 * MATB)      // 81920 B

__device__ __forceinline__ void gemm_hmma(const __nv_bfloat16* __restrict__ Ah,
                                          const __nv_bfloat16* __restrict__ Al,
                                          const __nv_bfloat16* __restrict__ Wh,
                                          const __nv_bfloat16* __restrict__ Wl,
                                          float* __restrict__ Cout,
                                          const float* __restrict__ bias)
{
    extern __shared__ char gsm[];
    const u32 sm = smem_u32(gsm);
    const int tid  = threadIdx.x;
    const int lane = tid & 31;
    const int wid  = tid >> 5;
    const int wm   = wid & 1;         // 2 m-slots of 64
    const int wn   = wid >> 1;        // 4 n-slots of 32
    const int mbase = blockIdx.y * 128;
    const int nbase = blockIdx.x * 128;

    // Staging map: 512 uint4 per matrix per chunk; thread does rows tid>>2 and +64.
    const int srow = tid >> 2;
    const int sc16 = tid & 3;
    const size_t gA0 = (size_t)(mbase + srow) * D_ + sc16 * 8;
    const size_t gW0 = (size_t)(nbase + srow) * D_ + sc16 * 8;
    const u32 so0 = (u32)(srow * LDKB + sc16 * 16);
    const u32 so1 = so0 + 64 * LDKB;
    const size_t gstep = (size_t)64 * D_;

    float acc[4][4][4];
    #pragma unroll
    for (int i = 0; i < 4; i++)
        #pragma unroll
        for (int j = 0; j < 4; j++)
            #pragma unroll
            for (int q = 0; q < 4; q++) acc[i][j][q] = 0.0f;

    // ldmatrix relative addresses (within one matrix buffer)
    const u32 arel = (u32)((wm * 64 + (lane & 15)) * LDKB + (lane >> 4) * 16);
    const u32 brel = (u32)((wn * 32 + (lane & 7))  * LDKB + ((lane >> 3) & 1) * 16);

    // ---- pipeline ----
    {   // stage chunk 0 -> buf 0
        cp16(sm + OAH + so0, Ah + gA0);          cp16(sm + OAH + so1, Ah + gA0 + gstep);
        cp16(sm + OAL + so0, Al + gA0);          cp16(sm + OAL + so1, Al + gA0 + gstep);
        cp16(sm + OWH + so0, Wh + gW0);          cp16(sm + OWH + so1, Wh + gW0 + gstep);
        cp16(sm + OWL + so0, Wl + gW0);          cp16(sm + OWL + so1, Wl + gW0 + gstep);
        CP_COMMIT();
    }

    for (int c = 0; c < 32; c++) {
        const int buf = c & 1;
        if (c + 1 < 32) {
            const u32 bo = (u32)((1 - buf) * MATB);
            const int kb = (c + 1) * 32;
            cp16(sm + OAH + bo + so0, Ah + gA0 + kb);  cp16(sm + OAH + bo + so1, Ah + gA0 + gstep + kb);
            cp16(sm + OAL + bo + so0, Al + gA0 + kb);  cp16(sm + OAL + bo + so1, Al + gA0 + gstep + kb);
            cp16(sm + OWH + bo + so0, Wh + gW0 + kb);  cp16(sm + OWH + bo + so1, Wh + gW0 + gstep + kb);
            cp16(sm + OWL + bo + so0, Wl + gW0 + kb);  cp16(sm + OWL + bo + so1, Wl + gW0 + gstep + kb);
            CP_COMMIT();
            CP_WAIT1();              // chunk c fully landed
        } else {
            CP_WAIT0();
        }
        __syncthreads();

        const u32 bofs = (u32)(buf * MATB);
        #pragma unroll
        for (int kh = 0; kh < 2; kh++) {          // two k16 halves of BK=32
            const u32 kofs = (u32)(kh * 32);      // 16 bf16 = 32 B
            u32 af[4][4], bh2[4][2], bl2[4][2];
            #pragma unroll
            for (int ni = 0; ni < 4; ni++) {
                ldm_x2(sm + OWH + bofs + brel + ni * (8 * LDKB) + kofs, bh2[ni][0], bh2[ni][1]);
                ldm_x2(sm + OWL + bofs + brel + ni * (8 * LDKB) + kofs, bl2[ni][0], bl2[ni][1]);
            }
            #pragma unroll
            for (int mi = 0; mi < 4; mi++)
                ldm_x4(sm + OAH + bofs + arel + mi * (16 * LDKB) + kofs,
                       af[mi][0], af[mi][1], af[mi][2], af[mi][3]);
            #pragma unroll
            for (int mi = 0; mi < 4; mi++)
                #pragma unroll
                for (int ni = 0; ni < 4; ni++) {
                    mma16816(acc[mi][ni], af[mi], bh2[ni]);
                    mma16816(acc[mi][ni], af[mi], bl2[ni]);
                }
            #pragma unroll
            for (int mi = 0; mi < 4; mi++)
                ldm_x4(sm + OAL + bofs + arel + mi * (16 * LDKB) + kofs,
                       af[mi][0], af[mi][1], af[mi][2], af[mi][3]);
            #pragma unroll
            for (int mi = 0; mi < 4; mi++)
                #pragma unroll
                for (int ni = 0; ni < 4; ni++)
                    mma16816(acc[mi][ni], af[mi], bh2[ni]);
        }
        __syncthreads();
    }

    // Epilogue: m16n8 C frag — lane g=lane>>2 rows {g, g+8}, cols ti*2+{0,1}.
    const int g  = lane >> 2;
    const int ti = lane & 3;
    #pragma unroll
    for (int mi = 0; mi < 4; mi++) {
        const int r0 = mbase + wm * 64 + mi * 16 + g;
        #pragma unroll
        for (int ni = 0; ni < 4; ni++) {
            const int col = nbase + wn * 32 + ni * 8 + ti * 2;
            float2 v0 = make_float2(acc[mi][ni][0], acc[mi][ni][1]);
            float2 v1 = make_float2(acc[mi][ni][2], acc[mi][ni][3]);
            if (bias) {
                const float b0 = bias[col], b1 = bias[col + 1];
                v0.x += b0; v0.y += b1;
                v1.x += b0; v1.y += b1;
            }
            *(float2*)(Cout + (size_t)r0 * D_ + col)       = v0;
            *(float2*)(Cout + (size_t)(r0 + 8) * D_ + col) = v1;
        }
    }
}

__global__ void __launch_bounds__(256) hmma_qkv_kernel()
{
    const int z = blockIdx.z;
    float* outp = (z == 0) ? g_Q : (z == 1) ? g_K : g_V;
    gemm_hmma(s_xh, s_xl, s_wh[z], s_wl[z], outp, nullptr);
}

__global__ void __launch_bounds__(256) hmma_out_kernel(float* __restrict__ out,
                                                       const float* __restrict__ bo)
{
    gemm_hmma(s_ch, s_cl, s_wh[3], s_wl[3], out, bo);
}

// ---------------------------------------------------------------------------
// bf16 hi/lo split of x and the four weight matrices.
// ---------------------------------------------------------------------------
__global__ void __launch_bounds__(256) split_kernel(const float* __restrict__ x,
                                                    const float* __restrict__ wq,
                                                    const float* __restrict__ wk,
                                                    const float* __restrict__ wv,
                                                    const float* __restrict__ wo)
{
    const int z = blockIdx.y;
    const float* src;
    __nv_bfloat16 *hi, *lo;
    int n;
    if (z == 0) { src = x; hi = s_xh; lo = s_xl; n = SZ_X; }
    else {
        src = (z == 1) ? wq : (z == 2) ? wk : (z == 3) ? wv : wo;
        hi = s_wh[z - 1]; lo = s_wl[z - 1]; n = SZ_W;
    }
    for (int i = blockIdx.x * 256 + threadIdx.x; i < n; i += gridDim.x * 256) {
        const float v = src[i];
        const __nv_bfloat16 h = __float2bfloat16(v);
        hi[i] = h;
        lo[i] = __float2bfloat16(v - __bfloat162float(h));
    }
}

// ---------------------------------------------------------------------------
// Flash attention (fp32, FFMA2), double-buffered 16-row KV tiles. Epilogue
// writes the bf16 hi/lo context split consumed by the HMMA out-projection.
// ---------------------------------------------------------------------------
__global__ void __launch_bounds__(128) flash_kernel()
{
    __shared__ float Ks[2][16][64];
    __shared__ float Vs[2][16][64];

    const int bh = blockIdx.y;
    const int b  = bh >> 4;
    const int h  = bh & 15;
    const int n  = blockIdx.x * 128 + threadIdx.x;
    const size_t row = (size_t)(b * N_ + n) * D_ + h * DH;

    u64 q2[32];
    {
        const float sc = 0.125f;
        #pragma unroll
        for (int d4 = 0; d4 < 16; d4++) {
            float4 t = *(const float4*)(g_Q + row + d4 * 4);
            q2[2 * d4]     = pack2(t.x * sc, t.y * sc);
            q2[2 * d4 + 1] = pack2(t.z * sc, t.w * sc);
        }
    }

    u64 o2[32];
    #pragma unroll
    for (int i = 0; i < 32; i++) o2[i] = 0ull;
    float m = -1e30f;
    float l = 0.0f;

    const size_t kvbase = (size_t)b * N_ * D_ + h * DH;

    const int f0  = threadIdx.x;
    const int f1  = threadIdx.x + 128;
    const int jr0 = f0 >> 4, c40 = (f0 & 15) * 4;
    const int jr1 = f1 >> 4, c41 = (f1 & 15) * 4;
    const size_t off0 = (size_t)jr0 * D_ + c40;
    const size_t off1 = (size_t)jr1 * D_ + c41;

    float4 kr0, kr1, vr0, vr1;

    kr0 = *(const float4*)(g_K + kvbase + off0);
    kr1 = *(const float4*)(g_K + kvbase + off1);
    vr0 = *(const float4*)(g_V + kvbase + off0);
    vr1 = *(const float4*)(g_V + kvbase + off1);
    *(float4*)&Ks[0][jr0][c40] = kr0;
    *(float4*)&Ks[0][jr1][c41] = kr1;
    *(float4*)&Vs[0][jr0][c40] = vr0;
    *(float4*)&Vs[0][jr1][c41] = vr1;
    __syncthreads();

    const int T = N_ / 16;
    for (int t = 0; t < T; t++) {
        const int cur = t & 1;

        if (t + 1 < T) {
            const size_t g = kvbase + (size_t)(t + 1) * 16 * D_;
            kr0 = *(const float4*)(g_K + g + off0);
            kr1 = *(const float4*)(g_K + g + off1);
            vr0 = *(const float4*)(g_V + g + off0);
            vr1 = *(const float4*)(g_V + g + off1);
        }

        float s[16];
        float tmax = -1e30f;
        #pragma unroll
        for (int j = 0; j < 16; j++) {
            const ulonglong2* kp = (const ulonglong2*)&Ks[cur][j][0];
            u64 a0 = 0ull, a1 = 0ull, a2 = 0ull, a3 = 0ull;
            #pragma unroll
            for (int e = 0; e < 16; e += 2) {
                ulonglong2 ka = kp[e];
                ulonglong2 kb = kp[e + 1];
                a0 = ffma2(q2[2 * e + 0], ka.x, a0);
                a1 = ffma2(q2[2 * e + 1], ka.y, a1);
                a2 = ffma2(q2[2 * e + 2], kb.x, a2);
                a3 = ffma2(q2[2 * e + 3], kb.y, a3);
            }
            float2 t0 = unpack2(a0), t1 = unpack2(a1);
            float2 t2 = unpack2(a2), t3 = unpack2(a3);
            s[j] = ((t0.x + t0.y) + (t1.x + t1.y)) + ((t2.x + t2.y) + (t3.x + t3.y));
            tmax = fmaxf(tmax, s[j]);
        }

        const float mnew = fmaxf(m, tmax);
        const float corr = __expf(m - mnew);
        m = mnew;
        float ps = 0.0f;
        #pragma unroll
        for (int j = 0; j < 16; j++) { s[j] = __expf(s[j] - mnew); ps += s[j]; }
        l = l * corr + ps;

        const u64 c2 = pack2(corr, corr);
        #pragma unroll
        for (int i = 0; i < 32; i++) o2[i] = fmul2(o2[i], c2);

        #pragma unroll
        for (int j = 0; j < 16; j++) {
            const u64 p2 = pack2(s[j], s[j]);
            const ulonglong2* vp = (const ulonglong2*)&Vs[cur][j][0];
            #pragma unroll
            for (int e = 0; e < 16; e++) {
                ulonglong2 vv = vp[e];
                o2[2 * e]     = ffma2(p2, vv.x, o2[2 * e]);
                o2[2 * e + 1] = ffma2(p2, vv.y, o2[2 * e + 1]);
            }
        }

        if (t + 1 < T) {
            const int nxt = 1 - cur;
            *(float4*)&Ks[nxt][jr0][c40] = kr0;
            *(float4*)&Ks[nxt][jr1][c41] = kr1;
            *(float4*)&Vs[nxt][jr0][c40] = vr0;
            *(float4*)&Vs[nxt][jr1][c41] = vr1;
        }
        __syncthreads();
    }

    // Normalize; write bf16 hi/lo split of the context row.
    const float inv = 1.0f / l;
    #pragma unroll
    for (int e = 0; e < 32; e++) {
        float2 v = unpack2(o2[e]);
        v.x *= inv; v.y *= inv;
        const __nv_bfloat16 hx = __float2bfloat16(v.x);
        const __nv_bfloat16 hy = __float2bfloat16(v.y);
        __nv_bfloat162 hp; hp.x = hx; hp.y = hy;
        __nv_bfloat162 lp;
        lp.x = __float2bfloat16(v.x - __bfloat162float(hx));
        lp.y = __float2bfloat16(v.y - __bfloat162float(hy));
        *(__nv_bfloat162*)(s_ch + row + 2 * e) = hp;
        *(__nv_bfloat162*)(s_cl + row + 2 * e) = lp;
    }
}

// ---------------------------------------------------------------------------
// Launch
// ---------------------------------------------------------------------------
extern "C" void kernel_launch(void* const* d_in, const int* in_sizes, int n_in,
                              void* d_out, int out_size)
{
    (void)in_sizes; (void)n_in; (void)out_size;
    const float* x  = (const float*)d_in[0];
    const float* Wq = (const float*)d_in[1];
    const float* Wk = (const float*)d_in[2];
    const float* Wv = (const float*)d_in[3];
    const float* Wo = (const float*)d_in[4];
    const float* bo = (const float*)d_in[5];
    float* out = (float*)d_out;

    cudaFuncSetAttribute(hmma_qkv_kernel,
                         cudaFuncAttributeMaxDynamicSharedMemorySize, GSMEM);
    cudaFuncSetAttribute(hmma_out_kernel,
                         cudaFuncAttributeMaxDynamicSharedMemorySize, GSMEM);

    split_kernel<<<dim3(1024, 5), 256>>>(x, Wq, Wk, Wv, Wo);

    hmma_qkv_kernel<<<dim3(D_ / 128, M_ / 128, 3), 256, GSMEM>>>();

    dim3 ga(N_ / 128, B_ * H_);
    flash_kernel<<<ga, 128>>>();

    hmma_out_kernel<<<dim3(D_ / 128, M_ / 128), 256, GSMEM>>>(out, bo);
}

// round 17
// speedup vs baseline: 2.5590x; 1.9147x over previous
#include <cuda_runtime.h>
#include <cuda_bf16.h>

// Problem constants
#define B_  2
#define N_  2048
#define D_  1024
#define H_  16
#define DH  64
#define M_  (B_ * N_)   // 4096 rows

#define SZ_X (M_ * D_)  // 4194304
#define SZ_W (D_ * D_)  // 1048576

// Scratch (device globals — no allocation allowed). All bf16 hi/lo splits.
__device__ __nv_bfloat16 s_xh[SZ_X], s_xl[SZ_X];
__device__ __nv_bfloat16 s_wh[4][SZ_W], s_wl[4][SZ_W];   // Wq,Wk,Wv,Wo
__device__ __nv_bfloat16 s_qh[SZ_X], s_ql[SZ_X];          // Q (pre-scaled by 1/8)
__device__ __nv_bfloat16 s_kh[SZ_X], s_kl[SZ_X];
__device__ __nv_bfloat16 s_vh[SZ_X], s_vl[SZ_X];
__device__ __nv_bfloat16 s_ch[SZ_X], s_cl[SZ_X];          // attention output split

typedef unsigned long long u64;
typedef unsigned int u32;

// ---------------------------------------------------------------------------
// HMMA plumbing (plain sm_80+ PTX — compiles for bare sm_103)
// ---------------------------------------------------------------------------
__device__ __forceinline__ u32 smem_u32(const void* p) {
    u32 a;
    asm("{ .reg .u64 t; cvta.to.shared.u64 t, %1; cvt.u32.u64 %0, t; }"
        : "=r"(a) : "l"(p));
    return a;
}
__device__ __forceinline__ void ldm_x4(u32 addr, u32& r0, u32& r1, u32& r2, u32& r3) {
    asm volatile("ldmatrix.sync.aligned.m8n8.x4.shared.b16 {%0,%1,%2,%3}, [%4];"
                 : "=r"(r0), "=r"(r1), "=r"(r2), "=r"(r3) : "r"(addr));
}
__device__ __forceinline__ void ldm_x2(u32 addr, u32& r0, u32& r1) {
    asm volatile("ldmatrix.sync.aligned.m8n8.x2.shared.b16 {%0,%1}, [%2];"
                 : "=r"(r0), "=r"(r1) : "r"(addr));
}
__device__ __forceinline__ void ldm_x2t(u32 addr, u32& r0, u32& r1) {
    asm volatile("ldmatrix.sync.aligned.m8n8.x2.trans.shared.b16 {%0,%1}, [%2];"
                 : "=r"(r0), "=r"(r1) : "r"(addr));
}
__device__ __forceinline__ void mma16816(float* d, const u32* a, const u32* b) {
    asm volatile("mma.sync.aligned.m16n8k16.row.col.f32.bf16.bf16.f32 "
                 "{%0,%1,%2,%3}, {%4,%5,%6,%7}, {%8,%9}, {%0,%1,%2,%3};"
                 : "+f"(d[0]), "+f"(d[1]), "+f"(d[2]), "+f"(d[3])
                 : "r"(a[0]), "r"(a[1]), "r"(a[2]), "r"(a[3]),
                   "r"(b[0]), "r"(b[1]));
}
__device__ __forceinline__ void cp16(u32 dst, const void* src) {
    asm volatile("cp.async.cg.shared.global [%0], [%1], 16;" :: "r"(dst), "l"(src));
}
#define CP_COMMIT() asm volatile("cp.async.commit_group;")
#define CP_WAIT1()  asm volatile("cp.async.wait_group 1;")
#define CP_WAIT0()  asm volatile("cp.async.wait_group 0;")

// Split float pair into bf16 hi (returned) and lo (residual) packed u32s.
__device__ __forceinline__ u32 split_pack(float x, float y, u32& lo) {
    __nv_bfloat162 hp = __floats2bfloat162_rn(x, y);
    const float rx = x - __bfloat162float(hp.x);
    const float ry = y - __bfloat162float(hp.y);
    __nv_bfloat162 lp = __floats2bfloat162_rn(rx, ry);
    lo = *(u32*)&lp;
    return *(u32*)&hp;
}

// ---------------------------------------------------------------------------
// HMMA GEMM: C[m][n] = sum_k A[m][k]*W[n][k], bf16x3 split, fp32 accumulate.
// BM=BN=128, BK=32, 256 threads (8 warps, 2x4 warp grid, warp tile 64x32).
// Epilogue: either fp32 (+bias) to Cout, or scaled bf16 hi/lo split to Hi/Lo.
// ---------------------------------------------------------------------------
#define LDKB 80               // padded smem row pitch in bytes (40 bf16)
#define MATB (128 * LDKB)     // 10240 B per matrix per buffer
#define OAH 0
#define OAL (2 * MATB)
#define OWH (4 * MATB)
#define OWL (6 * MATB)
#define GSMEM (8 * MATB)      // 81920 B

__device__ __forceinline__ void gemm_hmma(const __nv_bfloat16* __restrict__ Ah,
                                          const __nv_bfloat16* __restrict__ Al,
                                          const __nv_bfloat16* __restrict__ Wh,
                                          const __nv_bfloat16* __restrict__ Wl,
                                          float* __restrict__ Cout,
                                          const float* __restrict__ bias,
                                          __nv_bfloat16* __restrict__ Hi,
                                          __nv_bfloat16* __restrict__ Lo,
                                          float scale)
{
    extern __shared__ char gsm[];
    const u32 sm = smem_u32(gsm);
    const int tid  = threadIdx.x;
    const int lane = tid & 31;
    const int wid  = tid >> 5;
    const int wm   = wid & 1;
    const int wn   = wid >> 1;
    const int mbase = blockIdx.y * 128;
    const int nbase = blockIdx.x * 128;

    const int srow = tid >> 2;
    const int sc16 = tid & 3;
    const size_t gA0 = (size_t)(mbase + srow) * D_ + sc16 * 8;
    const size_t gW0 = (size_t)(nbase + srow) * D_ + sc16 * 8;
    const u32 so0 = (u32)(srow * LDKB + sc16 * 16);
    const u32 so1 = so0 + 64 * LDKB;
    const size_t gstep = (size_t)64 * D_;

    float acc[4][4][4];
    #pragma unroll
    for (int i = 0; i < 4; i++)
        #pragma unroll
        for (int j = 0; j < 4; j++)
            #pragma unroll
            for (int q = 0; q < 4; q++) acc[i][j][q] = 0.0f;

    const u32 arel = (u32)((wm * 64 + (lane & 15)) * LDKB + (lane >> 4) * 16);
    const u32 brel = (u32)((wn * 32 + (lane & 7))  * LDKB + ((lane >> 3) & 1) * 16);

    {   // stage chunk 0 -> buf 0
        cp16(sm + OAH + so0, Ah + gA0);          cp16(sm + OAH + so1, Ah + gA0 + gstep);
        cp16(sm + OAL + so0, Al + gA0);          cp16(sm + OAL + so1, Al + gA0 + gstep);
        cp16(sm + OWH + so0, Wh + gW0);          cp16(sm + OWH + so1, Wh + gW0 + gstep);
        cp16(sm + OWL + so0, Wl + gW0);          cp16(sm + OWL + so1, Wl + gW0 + gstep);
        CP_COMMIT();
    }

    for (int c = 0; c < 32; c++) {
        const int buf = c & 1;
        if (c + 1 < 32) {
            const u32 bo = (u32)((1 - buf) * MATB);
            const int kb = (c + 1) * 32;
            cp16(sm + OAH + bo + so0, Ah + gA0 + kb);  cp16(sm + OAH + bo + so1, Ah + gA0 + gstep + kb);
            cp16(sm + OAL + bo + so0, Al + gA0 + kb);  cp16(sm + OAL + bo + so1, Al + gA0 + gstep + kb);
            cp16(sm + OWH + bo + so0, Wh + gW0 + kb);  cp16(sm + OWH + bo + so1, Wh + gW0 + gstep + kb);
            cp16(sm + OWL + bo + so0, Wl + gW0 + kb);  cp16(sm + OWL + bo + so1, Wl + gW0 + gstep + kb);
            CP_COMMIT();
            CP_WAIT1();
        } else {
            CP_WAIT0();
        }
        __syncthreads();

        const u32 bofs = (u32)(buf * MATB);
        #pragma unroll
        for (int kh = 0; kh < 2; kh++) {
            const u32 kofs = (u32)(kh * 32);
            u32 af[4][4], bh2[4][2], bl2[4][2];
            #pragma unroll
            for (int ni = 0; ni < 4; ni++) {
                ldm_x2(sm + OWH + bofs + brel + ni * (8 * LDKB) + kofs, bh2[ni][0], bh2[ni][1]);
                ldm_x2(sm + OWL + bofs + brel + ni * (8 * LDKB) + kofs, bl2[ni][0], bl2[ni][1]);
            }
            #pragma unroll
            for (int mi = 0; mi < 4; mi++)
                ldm_x4(sm + OAH + bofs + arel + mi * (16 * LDKB) + kofs,
                       af[mi][0], af[mi][1], af[mi][2], af[mi][3]);
            #pragma unroll
            for (int mi = 0; mi < 4; mi++)
                #pragma unroll
                for (int ni = 0; ni < 4; ni++) {
                    mma16816(acc[mi][ni], af[mi], bh2[ni]);
                    mma16816(acc[mi][ni], af[mi], bl2[ni]);
                }
            #pragma unroll
            for (int mi = 0; mi < 4; mi++)
                ldm_x4(sm + OAL + bofs + arel + mi * (16 * LDKB) + kofs,
                       af[mi][0], af[mi][1], af[mi][2], af[mi][3]);
            #pragma unroll
            for (int mi = 0; mi < 4; mi++)
                #pragma unroll
                for (int ni = 0; ni < 4; ni++)
                    mma16816(acc[mi][ni], af[mi], bh2[ni]);
        }
        __syncthreads();
    }

    const int g  = lane >> 2;
    const int ti = lane & 3;
    #pragma unroll
    for (int mi = 0; mi < 4; mi++) {
        const int r0 = mbase + wm * 64 + mi * 16 + g;
        #pragma unroll
        for (int ni = 0; ni < 4; ni++) {
            const int col = nbase + wn * 32 + ni * 8 + ti * 2;
            float2 v0 = make_float2(acc[mi][ni][0], acc[mi][ni][1]);
            float2 v1 = make_float2(acc[mi][ni][2], acc[mi][ni][3]);
            if (Cout) {
                if (bias) {
                    const float b0 = bias[col], b1 = bias[col + 1];
                    v0.x += b0; v0.y += b1;
                    v1.x += b0; v1.y += b1;
                }
                *(float2*)(Cout + (size_t)r0 * D_ + col)       = v0;
                *(float2*)(Cout + (size_t)(r0 + 8) * D_ + col) = v1;
            } else {
                v0.x *= scale; v0.y *= scale; v1.x *= scale; v1.y *= scale;
                u32 lo0, lo1;
                const u32 hi0 = split_pack(v0.x, v0.y, lo0);
                const u32 hi1 = split_pack(v1.x, v1.y, lo1);
                *(u32*)(Hi + (size_t)r0 * D_ + col)       = hi0;
                *(u32*)(Lo + (size_t)r0 * D_ + col)       = lo0;
                *(u32*)(Hi + (size_t)(r0 + 8) * D_ + col) = hi1;
                *(u32*)(Lo + (size_t)(r0 + 8) * D_ + col) = lo1;
            }
        }
    }
}

__global__ void __launch_bounds__(256) hmma_qkv_kernel()
{
    const int z = blockIdx.z;
    __nv_bfloat16* hi = (z == 0) ? s_qh : (z == 1) ? s_kh : s_vh;
    __nv_bfloat16* lo = (z == 0) ? s_ql : (z == 1) ? s_kl : s_vl;
    const float sc = (z == 0) ? 0.125f : 1.0f;   // fold dh^-0.5 into Q
    gemm_hmma(s_xh, s_xl, s_wh[z], s_wl[z], nullptr, nullptr, hi, lo, sc);
}

__global__ void __launch_bounds__(256) hmma_out_kernel(float* __restrict__ out,
                                                       const float* __restrict__ bo)
{
    gemm_hmma(s_ch, s_cl, s_wh[3], s_wl[3], out, bo, nullptr, nullptr, 1.0f);
}

// ---------------------------------------------------------------------------
// bf16 hi/lo split of x and the four weight matrices.
// ---------------------------------------------------------------------------
__global__ void __launch_bounds__(256) split_kernel(const float* __restrict__ x,
                                                    const float* __restrict__ wq,
                                                    const float* __restrict__ wk,
                                                    const float* __restrict__ wv,
                                                    const float* __restrict__ wo)
{
    const int z = blockIdx.y;
    const float* src;
    __nv_bfloat16 *hi, *lo;
    int n;
    if (z == 0) { src = x; hi = s_xh; lo = s_xl; n = SZ_X; }
    else {
        src = (z == 1) ? wq : (z == 2) ? wk : (z == 3) ? wv : wo;
        hi = s_wh[z - 1]; lo = s_wl[z - 1]; n = SZ_W;
    }
    for (int i = blockIdx.x * 256 + threadIdx.x; i < n; i += gridDim.x * 256) {
        const float v = src[i];
        const __nv_bfloat16 h = __float2bfloat16(v);
        hi[i] = h;
        lo[i] = __float2bfloat16(v - __bfloat162float(h));
    }
}

// ---------------------------------------------------------------------------
// Tensor-core flash attention (FA-2), bf16x3 for BOTH QK^T and PV.
// Grid (N/128, B*H), 256 threads = 8 warps; warp w owns 16 query rows.
// KV chunks of 64 keys (Kh,Kl,Vh,Vl) cp.async double-buffered in smem,
// pitch 144 B (bank-skewed, conflict-free ldmatrix).
// ---------------------------------------------------------------------------
#define CH     64
#define FPITCH 144
#define FMATS  (64 * FPITCH)      // 9216 B per matrix
#define FBUF   (4 * FMATS)        // 36864 B per chunk buffer
#define FSMEM  (2 * FBUF)         // 73728 B

__global__ void __launch_bounds__(256) flash_mma_kernel()
{
    extern __shared__ char fsm[];
    const u32 sm = smem_u32(fsm);
    const int tid  = threadIdx.x;
    const int lane = tid & 31;
    const int w    = tid >> 5;
    const int g    = lane >> 2;
    const int ti   = lane & 3;
    const int bh = blockIdx.y;
    const int b  = bh >> 4;
    const int h  = bh & 15;
    const int qtok = b * N_ + blockIdx.x * 128 + w * 16;

    // ---- Q fragments (hi/lo), 4 k16 frags, direct from global ----
    u32 qh[4][4], ql[4][4];
    {
        const size_t r0 = (size_t)(qtok + g) * D_ + h * DH + ti * 2;
        const size_t r1 = (size_t)(qtok + g + 8) * D_ + h * DH + ti * 2;
        #pragma unroll
        for (int kf = 0; kf < 4; kf++) {
            qh[kf][0] = *(const u32*)(s_qh + r0 + kf * 16);
            qh[kf][1] = *(const u32*)(s_qh + r1 + kf * 16);
            qh[kf][2] = *(const u32*)(s_qh + r0 + kf * 16 + 8);
            qh[kf][3] = *(const u32*)(s_qh + r1 + kf * 16 + 8);
            ql[kf][0] = *(const u32*)(s_ql + r0 + kf * 16);
            ql[kf][1] = *(const u32*)(s_ql + r1 + kf * 16);
            ql[kf][2] = *(const u32*)(s_ql + r0 + kf * 16 + 8);
            ql[kf][3] = *(const u32*)(s_ql + r1 + kf * 16 + 8);
        }
    }

    float o[8][4];
    #pragma unroll
    for (int i = 0; i < 8; i++)
        #pragma unroll
        for (int q = 0; q < 4; q++) o[i][q] = 0.0f;
    float m0 = -1e30f, m1 = -1e30f, l0 = 0.0f, l1 = 0.0f;

    // ---- staging map: thread group (tid>>6) owns one of {Kh,Kl,Vh,Vl} ----
    const int smat = tid >> 6;
    const __nv_bfloat16* sbase = (smat == 0) ? s_kh : (smat == 1) ? s_kl
                               : (smat == 2) ? s_vh : s_vl;
    const int t64 = tid & 63;
    const size_t kvcol = (size_t)h * DH;

    // stage chunk 0 -> buf 0
    #pragma unroll
    for (int i = 0; i < 8; i++) {
        const int u2 = t64 + 64 * i;
        const int r = u2 >> 3, cc = u2 & 7;
        cp16(sm + smat * FMATS + r * FPITCH + cc * 16,
             sbase + (size_t)(b * N_ + r) * D_ + kvcol + cc * 8);
    }
    CP_COMMIT();

    const u32 krel = (u32)((lane & 7) * FPITCH + ((lane >> 3) & 1) * 16);
    const u32 vrel = (u32)((lane & 15) * FPITCH);

    for (int c = 0; c < N_ / CH; c++) {
        const int buf = c & 1;
        if (c + 1 < N_ / CH) {
            const u32 bo = (u32)((1 - buf) * FBUF);
            const int rowb = b * N_ + (c + 1) * CH;
            #pragma unroll
            for (int i = 0; i < 8; i++) {
                const int u2 = t64 + 64 * i;
                const int r = u2 >> 3, cc = u2 & 7;
                cp16(sm + bo + smat * FMATS + r * FPITCH + cc * 16,
                     sbase + (size_t)(rowb + r) * D_ + kvcol + cc * 8);
            }
            CP_COMMIT();
            CP_WAIT1();
        } else {
            CP_WAIT0();
        }
        __syncthreads();

        const u32 kb = sm + buf * FBUF;          // Kh; Kl at +FMATS
        const u32 vb = kb + 2 * FMATS;           // Vh; Vl at +FMATS

        // ---- S = Q.K^T (3-term bf16 split) ----
        float s[8][4];
        #pragma unroll
        for (int nf = 0; nf < 8; nf++)
            #pragma unroll
            for (int q = 0; q < 4; q++) s[nf][q] = 0.0f;

        #pragma unroll
        for (int nf = 0; nf < 8; nf++) {
            const u32 ka = kb + krel + nf * (8 * FPITCH);
            #pragma unroll
            for (int kf = 0; kf < 4; kf++) {
                u32 bh2[2], bl2[2];
                ldm_x2(ka + kf * 32, bh2[0], bh2[1]);
                ldm_x2(ka + FMATS + kf * 32, bl2[0], bl2[1]);
                mma16816(s[nf], qh[kf], bh2);
                mma16816(s[nf], qh[kf], bl2);
                mma16816(s[nf], ql[kf], bh2);
            }
        }

        // ---- online softmax (rows g and g+8) ----
        float mx0 = -1e30f, mx1 = -1e30f;
        #pragma unroll
        for (int nf = 0; nf < 8; nf++) {
            mx0 = fmaxf(mx0, fmaxf(s[nf][0], s[nf][1]));
            mx1 = fmaxf(mx1, fmaxf(s[nf][2], s[nf][3]));
        }
        mx0 = fmaxf(mx0, __shfl_xor_sync(0xffffffffu, mx0, 1));
        mx0 = fmaxf(mx0, __shfl_xor_sync(0xffffffffu, mx0, 2));
        mx1 = fmaxf(mx1, __shfl_xor_sync(0xffffffffu, mx1, 1));
        mx1 = fmaxf(mx1, __shfl_xor_sync(0xffffffffu, mx1, 2));

        const float mn0 = fmaxf(m0, mx0);
        const float mn1 = fmaxf(m1, mx1);
        const float cr0 = __expf(m0 - mn0);
        const float cr1 = __expf(m1 - mn1);
        m0 = mn0; m1 = mn1;

        float ps0 = 0.0f, ps1 = 0.0f;
        #pragma unroll
        for (int nf = 0; nf < 8; nf++) {
            s[nf][0] = __expf(s[nf][0] - mn0);
            s[nf][1] = __expf(s[nf][1] - mn0);
            s[nf][2] = __expf(s[nf][2] - mn1);
            s[nf][3] = __expf(s[nf][3] - mn1);
            ps0 += s[nf][0] + s[nf][1];
            ps1 += s[nf][2] + s[nf][3];
        }
        ps0 += __shfl_xor_sync(0xffffffffu, ps0, 1);
        ps0 += __shfl_xor_sync(0xffffffffu, ps0, 2);
        ps1 += __shfl_xor_sync(0xffffffffu, ps1, 1);
        ps1 += __shfl_xor_sync(0xffffffffu, ps1, 2);
        l0 = l0 * cr0 + ps0;
        l1 = l1 * cr1 + ps1;

        #pragma unroll
        for (int nd = 0; nd < 8; nd++) {
            o[nd][0] *= cr0; o[nd][1] *= cr0;
            o[nd][2] *= cr1; o[nd][3] *= cr1;
        }

        // ---- pack P into bf16 hi/lo A-frags (C-frag layout == A-frag layout) ----
        u32 ph[4][4], pl[4][4];
        #pragma unroll
        for (int kf = 0; kf < 4; kf++) {
            ph[kf][0] = split_pack(s[2 * kf][0],     s[2 * kf][1],     pl[kf][0]);
            ph[kf][1] = split_pack(s[2 * kf][2],     s[2 * kf][3],     pl[kf][1]);
            ph[kf][2] = split_pack(s[2 * kf + 1][0], s[2 * kf + 1][1], pl[kf][2]);
            ph[kf][3] = split_pack(s[2 * kf + 1][2], s[2 * kf + 1][3], pl[kf][3]);
        }

        // ---- O += P.V (3-term bf16 split, trans ldmatrix on V) ----
        #pragma unroll
        for (int nd = 0; nd < 8; nd++) {
            const u32 va = vb + vrel + nd * 16;
            #pragma unroll
            for (int kf = 0; kf < 4; kf++) {
                u32 bh2[2], bl2[2];
                ldm_x2t(va + kf * (16 * FPITCH), bh2[0], bh2[1]);
                ldm_x2t(va + FMATS + kf * (16 * FPITCH), bl2[0], bl2[1]);
                mma16816(o[nd], ph[kf], bh2);
                mma16816(o[nd], pl[kf], bh2);
                mma16816(o[nd], ph[kf], bl2);
            }
        }
        __syncthreads();
    }

    // ---- normalize; write bf16 hi/lo context ----
    const float i0 = 1.0f / l0;
    const float i1 = 1.0f / l1;
    const size_t r0 = (size_t)(qtok + g) * D_ + h * DH + ti * 2;
    const size_t r1 = (size_t)(qtok + g + 8) * D_ + h * DH + ti * 2;
    #pragma unroll
    for (int nd = 0; nd < 8; nd++) {
        u32 lo0, lo1;
        const u32 hi0 = split_pack(o[nd][0] * i0, o[nd][1] * i0, lo0);
        const u32 hi1 = split_pack(o[nd][2] * i1, o[nd][3] * i1, lo1);
        *(u32*)(s_ch + r0 + nd * 8) = hi0;
        *(u32*)(s_cl + r0 + nd * 8) = lo0;
        *(u32*)(s_ch + r1 + nd * 8) = hi1;
        *(u32*)(s_cl + r1 + nd * 8) = lo1;
    }
}

// ---------------------------------------------------------------------------
// Launch
// ---------------------------------------------------------------------------
extern "C" void kernel_launch(void* const* d_in, const int* in_sizes, int n_in,
                              void* d_out, int out_size)
{
    (void)in_sizes; (void)n_in; (void)out_size;
    const float* x  = (const float*)d_in[0];
    const float* Wq = (const float*)d_in[1];
    const float* Wk = (const float*)d_in[2];
    const float* Wv = (const float*)d_in[3];
    const float* Wo = (const float*)d_in[4];
    const float* bo = (const float*)d_in[5];
    float* out = (float*)d_out;

    cudaFuncSetAttribute(hmma_qkv_kernel,
                         cudaFuncAttributeMaxDynamicSharedMemorySize, GSMEM);
    cudaFuncSetAttribute(hmma_out_kernel,
                         cudaFuncAttributeMaxDynamicSharedMemorySize, GSMEM);
    cudaFuncSetAttribute(flash_mma_kernel,
                         cudaFuncAttributeMaxDynamicSharedMemorySize, FSMEM);

    split_kernel<<<dim3(1024, 5), 256>>>(x, Wq, Wk, Wv, Wo);

    hmma_qkv_kernel<<<dim3(D_ / 128, M_ / 128, 3), 256, GSMEM>>>();

    flash_mma_kernel<<<dim3(N_ / 128, B_ * H_), 256, FSMEM>>>();

    hmma_out_kernel<<<dim3(D_ / 128, M_ / 128), 256, GSMEM>>>(out, bo);
}